// round 17
// baseline (speedup 1.0000x reference)
#include <cuda_runtime.h>
#include <cuda_bf16.h>
#include <cstdint>

// ---------------------------------------------------------------------------
// DSS kernel via warp-level tensor cores (mma.sync bf16, baseline sm_80+ PTX).
//
// out[l,h] = Re( sum_n Wk[h,n] * z_{h,n}^l ),  l = 32*j + dl  (j<64, dl<32).
//   A_h[j, k]  (M=64 x K=128) : k=2n -> Re(Wk z^32j), k=2n+1 -> Im(Wk z^32j)
//   B_h[dl, k] (N=32 x K=128) : k=2n -> Re(z^dl),     k=2n+1 -> -Im(z^dl)
//   D = A . B^T (fp32 accum)  => out[32j+dl, h].
// bf16 hi/lo split: D = Ah.Bh + Al.Bh + Ah.Bl.
// CTA = 4 h (sequential), 256 thr, 2 CTAs/SM; warp = (M-tile 0..3, N-half).
// Chunk-major MMA (each fragment loaded once). NO smem stage: the 4 hh
// results per output position are kept in registers across the hh loop and
// stored as one float4 (out[l, h0..h0+3]) directly to gmem.
// ---------------------------------------------------------------------------

#define EPS2 1e-14f

#define FH 1024
#define FN 64
#define FL 2048

#define INV_2PI 0.15915494309189535f
#define PI2_HI  6.2831854820251465f
#define PI2_LO  (-1.7484556000744483e-7f)

// ---- smem layout (bytes). A/B rows padded to 264 bf16 = 528 B ----
#define APITCH     528
#define SMEM_A     0                       // 64 x 528 = 33792
#define SMEM_B     33792                   // 32 x 528 = 16896
#define SMEM_CA    50688                   // float4[256] = 4096
#define SMEM_CG    54784                   // float2[256] = 2048
#define SMEM_TOTAL 56832

// ---- PTX helpers ----
__device__ __forceinline__ uint32_t smem_u32(const void* p) {
    uint32_t a;
    asm("{ .reg .u64 t; cvta.to.shared.u64 t, %1; cvt.u32.u64 %0, t; }"
        : "=r"(a) : "l"(p));
    return a;
}

#define LDMATRIX_X4(r0, r1, r2, r3, addr)                                    \
    asm volatile("ldmatrix.sync.aligned.m8n8.x4.shared.b16 {%0,%1,%2,%3}, [%4];" \
        : "=r"(r0), "=r"(r1), "=r"(r2), "=r"(r3) : "r"(addr))

#define MMA_BF16(d, a0, a1, a2, a3, b0, b1)                                  \
    asm volatile("mma.sync.aligned.m16n8k16.row.col.f32.bf16.bf16.f32 "      \
        "{%0,%1,%2,%3}, {%4,%5,%6,%7}, {%8,%9}, {%0,%1,%2,%3};"              \
        : "+f"((d)[0]), "+f"((d)[1]), "+f"((d)[2]), "+f"((d)[3])             \
        : "r"(a0), "r"(a1), "r"(a2), "r"(a3), "r"(b0), "r"(b1))

// packs r = {hi: bf16(y), lo: bf16(x)}  (memory order: x then y)
#define CVT2(r, x, y) asm("cvt.rn.satfinite.bf16x2.f32 %0, %1, %2;" : "=r"(r) : "f"(y), "f"(x))

// fast sin/cos with Cody-Waite reduction to [-pi, pi]
__device__ __forceinline__ void fast_sincos(float th, float* s, float* c)
{
    float k = rintf(th * INV_2PI);
    float r = fmaf(-k, PI2_HI, th);
    r = fmaf(-k, PI2_LO, r);
    *s = __sinf(r);
    *c = __cosf(r);
}
// same reduction, precise sincosf on the small residue
__device__ __forceinline__ void cw_sincos(float th, float* s, float* c)
{
    float k = rintf(th * INV_2PI);
    float r = fmaf(-k, PI2_HI, th);
    r = fmaf(-k, PI2_LO, r);
    sincosf(r, s, c);
}

// ---------------------------------------------------------------------------
__global__ void __launch_bounds__(256, 2) k_tc(
    const float* __restrict__ log_dt,
    const float* __restrict__ llnr,
    const float* __restrict__ lim,
    const float* __restrict__ W,
    float* __restrict__ out)
{
    extern __shared__ char smem[];
    const uint32_t sb = smem_u32(smem);
    const int tid  = threadIdx.x;
    const int wid  = tid >> 5;
    const int lane = tid & 31;
    const int h0   = blockIdx.x * 4;

    float4* cA = (float4*)(smem + SMEM_CA);   // (a, b, m16r, m16i)
    float2* cG = (float2*)(smem + SMEM_CG);   // (Wk_re, Wk_im)

    // ---- P1: per-(hh, n) constants, one per thread ---------------------------
    {
        int idx = tid;                      // 256 = 4 hh x 64 n
        int hh = idx >> 6, n = idx & 63;
        int h = h0 + hh;

        float lr = -expf(llnr[n]);
        float li = lim[n];
        float dtr = expf(log_dt[2 * h + 0]);
        float dti = expf(log_dt[2 * h + 1]);
        float a = dtr * lr;        // < 0
        float b = dti * li;

        // Wk = Wc * (exp(dtL)-1) * reciprocal_clamped(Lambda)
        float ns = fmaxf(lr * lr + li * li, EPS2);
        float rr =  lr / ns;
        float ri = -li / ns;
        float ea = expf(a), sbf, cbf;
        sincosf(b, &sbf, &cbf);
        float edr = ea * cbf - 1.0f;
        float edi = ea * sbf;
        float wr = W[(h * FN + n) * 2 + 0];
        float wi = W[(h * FN + n) * 2 + 1];
        float tr = wr * edr - wi * edi;
        float ti = wr * edi + wi * edr;
        float gr = tr * rr - ti * ri;
        float gi = tr * ri + ti * rr;

        // m16 = z^16 (CW-reduced angle, precise sincos)
        float s16, c16;
        cw_sincos(16.0f * b, &s16, &c16);
        float e16 = expf(16.0f * a);

        cA[idx] = make_float4(a, b, e16 * c16, e16 * s16);
        cG[idx] = make_float2(gr, gi);
    }
    __syncthreads();

    // warp roles: m-tile = wid & 3 (j rows 16m..), n-half = wid >> 2 (dl 16nh..)
    const int mtl = wid & 3;
    const int nhf = wid >> 2;

    const uint32_t a_lanebase = sb + SMEM_A
        + (uint32_t)(16 * mtl + (lane & 15)) * APITCH + ((lane >> 4) << 4);
    const uint32_t b_lanebase = sb + SMEM_B
        + (uint32_t)(16 * nhf + ((lane >> 4) & 1) * 8 + (lane & 7)) * APITCH
        + (((lane >> 3) & 1) << 4);

    const int n_ = tid & 63;
    const int q_ = tid >> 6;     // j-quarter 0..3 (16 j each)

    // output fragments for all 4 hh, kept in registers
    float dall[8][4];

    for (int hh = 0; hh < 4; hh++) {
        // ---- build A: S_j = Wk * z^(32 j); thread does j = 16 q_ .. +15 ------
        {
            float4 ab = cA[hh * 64 + n_];
            float2 G  = cG[hh * 64 + n_];
            float Sr = G.x, Si = G.y;
            if (q_) {            // rotate by z^(512 q_)
                float mult = 512.0f * (float)q_;
                float s, c;
                fast_sincos(ab.y * mult, &s, &c);
                float e = __expf(ab.x * mult);
                float zr = e * c, zi = e * s;
                float t = Sr * zr - Si * zi;
                Si = Sr * zi + Si * zr;
                Sr = t;
            }
            // m32 = m16^2
            const float mr = ab.z * ab.z - ab.w * ab.w;
            const float mi = 2.0f * ab.z * ab.w;
            uint32_t wbase = sb + SMEM_A + (uint32_t)(q_ * 16) * APITCH + 4u * n_;
#pragma unroll 8
            for (int s = 0; s < 16; s++) {
                uint32_t rh;
                CVT2(rh, Sr, Si);
                float frh = __uint_as_float(rh << 16);
                float fih = __uint_as_float(rh & 0xFFFF0000u);
                uint32_t rl;
                CVT2(rl, Sr - frh, Si - fih);
                asm volatile("st.shared.b32 [%0], %1;" :: "r"(wbase), "r"(rh) : "memory");
                asm volatile("st.shared.b32 [%0], %1;" :: "r"(wbase + 256u), "r"(rl) : "memory");
                wbase += APITCH;
                float t = Sr * mr - Si * mi;
                Si = Sr * mi + Si * mr;
                Sr = t;
            }
        }
        // ---- build B: (Re z^dl, -Im z^dl); threads 0..127 = (dh, n) ----------
        if (tid < 128) {
            const int dh = tid >> 6;        // dl-half 0/1
            float4 ab = cA[hh * 64 + n_];
            float e = __expf(ab.x);
            float s, c;
            fast_sincos(ab.y, &s, &c);
            float zr = e * c, zi = e * s;
            float Er, Ei;
            if (dh) { Er = ab.z;  Ei = ab.w; }   // z^16
            else    { Er = 1.0f;  Ei = 0.0f; }
            uint32_t wbase = sb + SMEM_B + (uint32_t)(dh * 16) * APITCH + 4u * n_;
#pragma unroll
            for (int dl = 0; dl < 16; dl++) {
                float vr = Er, vi = -Ei;
                uint32_t rh;
                CVT2(rh, vr, vi);
                float frh = __uint_as_float(rh << 16);
                float fih = __uint_as_float(rh & 0xFFFF0000u);
                uint32_t rl;
                CVT2(rl, vr - frh, vi - fih);
                asm volatile("st.shared.b32 [%0], %1;" :: "r"(wbase), "r"(rh) : "memory");
                asm volatile("st.shared.b32 [%0], %1;" :: "r"(wbase + 256u), "r"(rl) : "memory");
                wbase += APITCH;
                float t = Er * zr - Ei * zi;
                Ei = Er * zi + Ei * zr;
                Er = t;
            }
        }
        __syncthreads();

        // ---- MMA: chunk-major; 4 ldmatrix.x4 + 6 MMAs per k-chunk ------------
        float d0[4] = {0.f, 0.f, 0.f, 0.f};
        float d1[4] = {0.f, 0.f, 0.f, 0.f};
#pragma unroll
        for (int c = 0; c < 8; c++) {
            uint32_t ah0, ah1, ah2, ah3, al0, al1, al2, al3;
            uint32_t bh0, bh1, bh2, bh3, bl0, bl1, bl2, bl3;
            LDMATRIX_X4(ah0, ah1, ah2, ah3, a_lanebase + 32u * c);          // A hi
            LDMATRIX_X4(al0, al1, al2, al3, a_lanebase + 256u + 32u * c);   // A lo
            LDMATRIX_X4(bh0, bh1, bh2, bh3, b_lanebase + 32u * c);          // B hi
            LDMATRIX_X4(bl0, bl1, bl2, bl3, b_lanebase + 256u + 32u * c);   // B lo
            MMA_BF16(d0, ah0, ah1, ah2, ah3, bh0, bh1);
            MMA_BF16(d1, ah0, ah1, ah2, ah3, bh2, bh3);
            MMA_BF16(d0, al0, al1, al2, al3, bh0, bh1);
            MMA_BF16(d1, al0, al1, al2, al3, bh2, bh3);
            MMA_BF16(d0, ah0, ah1, ah2, ah3, bl0, bl1);
            MMA_BF16(d1, ah0, ah1, ah2, ah3, bl2, bl3);
        }

        // ---- keep this hh's fragments in registers ---------------------------
#pragma unroll
        for (int e = 0; e < 4; e++) {
            dall[e][hh]     = d0[e];
            dall[4 + e][hh] = d1[e];
        }
        __syncthreads();   // all A/B reads done before next-h rebuild
    }

    // ---- final store: 8 x float4 -> out[l, h0..h0+3] -------------------------
    {
        const int g  = lane >> 2;
        const int tc = lane & 3;
        const int j0 = 16 * mtl + g;
        const int j1 = j0 + 8;
        const int dA = 16 * nhf + 2 * tc;
        const int dB = dA + 8;
        const int lpos[8] = {
            j0 * 32 + dA, j0 * 32 + dA + 1, j1 * 32 + dA, j1 * 32 + dA + 1,
            j0 * 32 + dB, j0 * 32 + dB + 1, j1 * 32 + dB, j1 * 32 + dB + 1
        };
#pragma unroll
        for (int e = 0; e < 8; e++) {
            float4 v = make_float4(dall[e][0], dall[e][1], dall[e][2], dall[e][3]);
            *reinterpret_cast<float4*>(out + (size_t)lpos[e] * FH + h0) = v;
        }
    }
}

// ---------------------------------------------------------------------------
// Generic fallback (correct for any shape; slow).
// ---------------------------------------------------------------------------
__global__ void k_generic(const float* __restrict__ log_dt,
                          const float* __restrict__ llnr,
                          const float* __restrict__ lim,
                          const float* __restrict__ W,
                          float* __restrict__ out,
                          int H, int N, int L)
{
    int idx = blockIdx.x * blockDim.x + threadIdx.x;
    if (idx >= L * H) return;
    int l = idx / H, h = idx - l * H;
    float dtr = expf(log_dt[2 * h + 0]);
    float dti = expf(log_dt[2 * h + 1]);
    float fl = (float)l;
    float sum = 0.0f;
    for (int n = 0; n < N; n++) {
        float lr = -expf(llnr[n]);
        float li = lim[n];
        float a = dtr * lr, b = dti * li;
        float ns = fmaxf(lr * lr + li * li, EPS2);
        float rr = lr / ns, ri = -li / ns;
        float ea = expf(a), sb, cb;
        sincosf(b, &sb, &cb);
        float edr = ea * cb - 1.0f, edi = ea * sb;
        float wr = W[(h * N + n) * 2 + 0], wi = W[(h * N + n) * 2 + 1];
        float tr = wr * edr - wi * edi, ti = wr * edi + wi * edr;
        float wkr = tr * rr - ti * ri, wki = tr * ri + ti * rr;
        float el = expf(a * fl), sl, cl;
        sincosf(b * fl, &sl, &cl);
        sum += wkr * (el * cl) - wki * (el * sl);
    }
    out[idx] = sum;
}

// ---------------------------------------------------------------------------
extern "C" void kernel_launch(void* const* d_in, const int* in_sizes, int n_in,
                              void* d_out, int out_size)
{
    const float* log_dt = (const float*)d_in[0];   // (H,2)
    const float* llnr   = (const float*)d_in[1];   // (N,)
    const float* lim    = (const float*)d_in[2];   // (N,)
    const float* W      = (const float*)d_in[3];   // (H,N,2)
    float* out = (float*)d_out;

    int H = in_sizes[0] / 2;
    int N = in_sizes[1];
    int L = out_size / H;

    if (H == FH && N == FN && L == FL) {
        cudaFuncSetAttribute(k_tc, cudaFuncAttributeMaxDynamicSharedMemorySize,
                             SMEM_TOTAL);
        k_tc<<<FH / 4, 256, SMEM_TOTAL>>>(log_dt, llnr, lim, W, out);
    } else {
        int tot = L * H;
        k_generic<<<(tot + 255) / 256, 256>>>(log_dt, llnr, lim, W, out, H, N, L);
    }
}